// round 10
// baseline (speedup 1.0000x reference)
#include <cuda_runtime.h>
#include <math.h>

#define BB 16
#define CIN 3
#define HIDC 64
#define SS 16384
#define QQ 4096               // SS/4
#define MM 16
#define LL 4
#define NPSP 500
#define NPFR 200
#define EDIM 8
#define NHEADS 4
#define CHPH 16               // channels per head
#define NSPLIT 64             // DFT partial splits per channel
#define NIDXC 8               // idx-kernel chunks

// ---------------- scratch (device globals; no allocation) ----------------
__device__ float d_mC[QQ * MM];                          // cos(2*pi*q*m/S)
__device__ float d_mS[QQ * MM];                          // sin(2*pi*q*m/S)
__device__ float d_h[BB * SS * HIDC];                    // activation, [b][s][d]
__device__ float d_sC[BB * SS];                          // channel-sum of h
__device__ int   d_idx[BB * SS];                         // spatial hash indices
__device__ float d_Xpart[BB * HIDC * NSPLIT * 32];       // DFT partials (8 MB)
__device__ float d_esum[BB * NIDXC * EDIM];              // partial emb sums
__device__ float d_cA[BB * HIDC * MM];                   // fused cos coefficients
__device__ float d_cB[BB * HIDC * MM];                   // fused sin coefficients
__device__ float d_spw2[BB * HIDC * EDIM];               // gate-folded spatial W
__device__ float d_spb2[BB * HIDC];                      // gate-folded spatial b
__device__ float d_spT[BB * NPSP * HIDC];                // per-pattern sp+DC table

__device__ __forceinline__ float gelu_exact(float v) {
    return 0.5f * v * (1.0f + erff(v * 0.70710678118654752f));
}

// ---------------- mode-trig tables (exact base angles) ----------------
__global__ void k_table() {
    int i = blockIdx.x * blockDim.x + threadIdx.x;   // < QQ*MM
    int q = i >> 4, m = i & 15;
    int r = (q * m) & (SS - 1);
    double a = 6.283185307179586476925286766559 * (double)r / (double)SS;
    d_mC[i] = (float)cos(a);
    d_mS[i] = (float)sin(a);
}

// ---------------- lifting: x[B,3,S] -> h[b][s][d], plus channel-sum ----------------
__global__ __launch_bounds__(256) void k_lift(const float* __restrict__ x,
                                              const float* __restrict__ W,
                                              const float* __restrict__ bv) {
    __shared__ float sW[CIN * HIDC];
    __shared__ float sB[HIDC];
    int t = threadIdx.x;
    if (t < CIN * HIDC) sW[t] = W[t];
    if (t < HIDC) sB[t] = bv[t];
    __syncthreads();
    int b = blockIdx.x;
    int s = blockIdx.y * 256 + t;
    float x0 = x[(b * CIN + 0) * SS + s];
    float x1 = x[(b * CIN + 1) * SS + s];
    float x2 = x[(b * CIN + 2) * SS + s];
    float sc = 0.f;
    float4* hp = (float4*)(d_h + ((size_t)b * SS + s) * HIDC);
#pragma unroll
    for (int j = 0; j < HIDC / 4; j++) {
        float4 v;
        float* vv = (float*)&v;
#pragma unroll
        for (int u = 0; u < 4; u++) {
            int d = j * 4 + u;
            float w = sB[d];
            w = fmaf(x0, sW[0 * HIDC + d], w);
            w = fmaf(x1, sW[1 * HIDC + d], w);
            w = fmaf(x2, sW[2 * HIDC + d], w);
            vv[u] = w; sc += w;
        }
        hp[j] = v;
    }
    d_sC[b * SS + s] = sc;
}

// ---------------- spatial hash indices + embedding mean partials ----------------
__global__ __launch_bounds__(256) void k_idx(const float* __restrict__ spEmb) {
    int b = blockIdx.x;
    int chunk = blockIdx.y;
    int t = threadIdx.x;
    const float* sc = d_sC + b * SS;
    float es[EDIM];
#pragma unroll
    for (int k = 0; k < EDIM; k++) es[k] = 0.f;
    const int span = SS / NIDXC;        // 2048
    for (int it = 0; it < span / 256; it++) {
        int s = chunk * span + it * 256 + t;
        int sm2 = max(s - 2, 0), sm1 = max(s - 1, 0), sp1 = min(s + 1, SS - 1);
        float w = sc[sm2] + sc[sm1] + sc[s] + sc[sp1];
        int iv = (int)(w * 31.0f);      // trunc toward zero
        iv %= NPSP; if (iv < 0) iv += NPSP;
        d_idx[b * SS + s] = iv;
        const float* e = spEmb + iv * EDIM;
#pragma unroll
        for (int k = 0; k < EDIM; k++) es[k] += __ldg(e + k);
    }
    __shared__ float red[256][EDIM];
#pragma unroll
    for (int k = 0; k < EDIM; k++) red[t][k] = es[k];
    __syncthreads();
    for (int off = 128; off > 0; off >>= 1) {
        if (t < off) {
#pragma unroll
            for (int k = 0; k < EDIM; k++) red[t][k] += red[t + off][k];
        }
        __syncthreads();
    }
    if (t < EDIM) d_esum[(b * NIDXC + chunk) * EDIM + t] = red[0][t];
}

// ---------------- 16-mode DFT: thread-per-channel, table trig, quartet fold ------
// I accumulates +sum h*sin (negated later in k_coeff).
__global__ __launch_bounds__(128) void k_dft() {
    int b = blockIdx.x, chunk = blockIdx.y;       // chunk 0..31
    int t = threadIdx.x, d = t & 63, qg = t >> 6; // qg 0..1
    int split = chunk * 2 + qg;                   // 0..63
    const float* hb = d_h + (size_t)b * SS * HIDC + d;
    float aR[MM], aI[MM];
#pragma unroll
    for (int m = 0; m < MM; m++) { aR[m] = 0.f; aI[m] = 0.f; }
    int q0 = split * 64;
#pragma unroll 2
    for (int i = 0; i < 64; i++) {
        int q = q0 + i;
        if (q == 0) {
            float u = hb[0];
            float w = hb[(size_t)4096 * HIDC];
            float v = hb[(size_t)8192 * HIDC];
            float z = hb[(size_t)12288 * HIDC];
            float wzp = w + z, wzm = w - z;
#pragma unroll
            for (int m = 0; m < MM; m++) {
                aR[m] += u + ((m & 1) ? -v : v);
                int mm = m & 3;
                if (mm == 0)      aR[m] += wzp;
                else if (mm == 2) aR[m] -= wzp;
                else if (mm == 1) aI[m] += wzm;
                else              aI[m] -= wzm;
            }
            continue;
        }
        float ha  = hb[(size_t)q * HIDC];
        float hbv = hb[(size_t)(8192 - q) * HIDC];
        float hc  = hb[(size_t)(8192 + q) * HIDC];
        float he  = hb[(size_t)(16384 - q) * HIDC];
        float p = ha + he, qv = hbv + hc, r = ha - he, tv = hc - hbv;
        float xe = p + qv, xo = p - qv, ye = r + tv, yo = r - tv;
        const float* Cq = d_mC + q * MM;
        const float* Sq = d_mS + q * MM;
        aR[0] += xe;
#pragma unroll
        for (int m = 1; m < MM; m++) {
            float cm = __ldg(Cq + m), sm = __ldg(Sq + m);
            if (m & 1) { aR[m] = fmaf(cm, xo, aR[m]); aI[m] = fmaf(sm, yo, aI[m]); }
            else       { aR[m] = fmaf(cm, xe, aR[m]); aI[m] = fmaf(sm, ye, aI[m]); }
        }
    }
    float* o = d_Xpart + ((size_t)(b * HIDC + d) * NSPLIT + split) * 32;
#pragma unroll
    for (int m = 0; m < MM; m++) { o[2 * m] = aR[m]; o[2 * m + 1] = aI[m]; }
}

// ---------------- per-batch: reduce X, mh mixing, fr hash, gating, coefficients ----------------
__global__ __launch_bounds__(256) void k_coeff(int layer,
        const float* __restrict__ frEmb, const float* __restrict__ frW, const float* __restrict__ frB,
        const float* __restrict__ spW, const float* __restrict__ spB,
        const float* __restrict__ gW1, const float* __restrict__ gB1,
        const float* __restrict__ gW2, const float* __restrict__ gB2,
        const float* __restrict__ Wr, const float* __restrict__ Wi) {
    int b = blockIdx.x, t = threadIdx.x;
    __shared__ float sXr[HIDC][MM], sXi[HIDC][MM];
    __shared__ float sOr[HIDC][MM], sOi[HIDC][MM];
    __shared__ float sP[HIDC][MM];
    __shared__ int   smagi[MM];
    __shared__ int   sIdxFr;
    __shared__ float sEbar[EDIM];
    __shared__ float sg[3 * HIDC];
    __shared__ float sh1[HIDC];
    __shared__ float swv[3];

    // A: reduce DFT partials (fixed order), negate imag to true sign
    for (int jg = t; jg < HIDC * 32; jg += 256) {
        int c = jg >> 5, j = jg & 31;
        float s = 0.f;
        const float* p = d_Xpart + (size_t)(b * HIDC + c) * NSPLIT * 32 + j;
#pragma unroll 8
        for (int q = 0; q < NSPLIT; q++) s += p[q * 32];
        int m = j >> 1;
        if (j & 1) sXi[c][m] = -s; else sXr[c][m] = s;
    }
    __syncthreads();
    // B: spectral hash
    if (t < MM) {
        float acc = 0.f;
        for (int c = 0; c < HIDC; c++) {
            float xr = sXr[c][t], xi = sXi[c][t];
            acc += sqrtf(xr * xr + xi * xi);
        }
        float mag = acc * (1.0f / 64.0f);
        smagi[t] = (int)(mag * 1000.0f);
    }
    __syncthreads();
    if (t == 0) {
        int tot = 0;
#pragma unroll
        for (int m = 0; m < MM; m++) tot += smagi[m];
        tot %= NPFR; if (tot < 0) tot += NPFR;
        sIdxFr = tot;
    }
    if (t >= 32 && t < 32 + EDIM) {
        int k = t - 32; float s = 0.f;
        for (int p = 0; p < NIDXC; p++) s += d_esum[(b * NIDXC + p) * EDIM + k];
        sEbar[k] = s * (1.0f / (float)SS);
    }
    __syncthreads();
    // C: fr projection P[c][m]
    {
        float ef[EDIM];
        const float* er = frEmb + (layer * NPFR + sIdxFr) * EDIM;
#pragma unroll
        for (int k = 0; k < EDIM; k++) ef[k] = __ldg(er + k);
        for (int o = t; o < HIDC * MM; o += 256) {
            float v = frB[layer * HIDC * MM + o];
#pragma unroll
            for (int k = 0; k < EDIM; k++)
                v = fmaf(ef[k], frW[(layer * EDIM + k) * HIDC * MM + o], v);
            sP[o >> 4][o & 15] = v;
        }
    }
    // D: complex head mixing O = X W  (W[L][H][i][o][m])
    for (int q = t; q < HIDC * MM; q += 256) {
        int hh = q >> 8;
        int o = (q >> 4) & 15;
        int m = q & 15;
        float ar = 0.f, ai = 0.f;
        const float* wr = Wr + (((size_t)(layer * NHEADS + hh) * CHPH) * CHPH + o) * MM + m;
        const float* wi = Wi + (((size_t)(layer * NHEADS + hh) * CHPH) * CHPH + o) * MM + m;
#pragma unroll
        for (int i = 0; i < CHPH; i++) {
            float xr = sXr[hh * CHPH + i][m], xi = sXi[hh * CHPH + i][m];
            float wrv = wr[i * CHPH * MM], wiv = wi[i * CHPH * MM];
            ar = fmaf(xr, wrv, ar); ar = fmaf(-xi, wiv, ar);
            ai = fmaf(xr, wiv, ai); ai = fmaf(xi, wrv, ai);
        }
        sOr[hh * CHPH + o][m] = ar;
        sOi[hh * CHPH + o][m] = ai;
    }
    __syncthreads();
    // E: gating (analytic branch means)
    if (t < 3 * HIDC) {
        float v;
        if (t < HIDC) {
            v = spB[layer * HIDC + t];
#pragma unroll
            for (int k = 0; k < EDIM; k++)
                v = fmaf(sEbar[k], spW[(layer * EDIM + k) * HIDC + t], v);
        } else if (t < 2 * HIDC) {
            v = sOr[t - HIDC][0] * (1.0f / (float)SS);
        } else {
            v = sP[t - 2 * HIDC][0] * (1.0f / (float)SS);
        }
        sg[t] = v;
    }
    __syncthreads();
    if (t < HIDC) {
        float v = gB1[layer * 64 + t];
        for (int k = 0; k < 3 * HIDC; k++)
            v = fmaf(sg[k], gW1[(layer * 3 * HIDC + k) * 64 + t], v);
        sh1[t] = fmaxf(v, 0.f);
    }
    __syncthreads();
    if (t < 3) {
        float v = gB2[layer * 3 + t];
        for (int k = 0; k < HIDC; k++)
            v = fmaf(sh1[k], gW2[(layer * HIDC + k) * 3 + t], v);
        swv[t] = v;
    }
    __syncthreads();
    if (t == 0) {
        float mx = fmaxf(swv[0], fmaxf(swv[1], swv[2]));
        float e0 = expf(swv[0] - mx), e1 = expf(swv[1] - mx), e2 = expf(swv[2] - mx);
        float inv = 1.f / (e0 + e1 + e2);
        swv[0] = e0 * inv; swv[1] = e1 * inv; swv[2] = e2 * inv;
    }
    __syncthreads();
    // F: gate-folded synthesis coefficients
    if (t < HIDC) {
        int d = t;
        float w0 = swv[0], w1 = swv[1], w2 = swv[2];
        const float invS = 1.0f / (float)SS;
        float* A = d_cA + (b * HIDC + d) * MM;
        float* Bc = d_cB + (b * HIDC + d) * MM;
        A[0] = invS * (w1 * sOr[d][0] + w2 * sP[d][0]);
        Bc[0] = 0.f;
#pragma unroll
        for (int m = 1; m < MM; m++) {
            A[m] = 2.f * invS * (w1 * sOr[d][m] + w2 * sP[d][m]);
            Bc[m] = -2.f * invS * w1 * sOi[d][m];
        }
#pragma unroll
        for (int k = 0; k < EDIM; k++)
            d_spw2[(b * HIDC + d) * EDIM + k] = w0 * spW[(layer * EDIM + k) * HIDC + d];
        d_spb2[b * HIDC + d] = w0 * spB[layer * HIDC + d];
    }
}

// ---------------- per-layer spatial+DC table: T[b][p][d] = spb2 + A0 + emb[p]@spw2 ----
__global__ __launch_bounds__(256) void k_spt(const float* __restrict__ spEmb) {
    int b = blockIdx.x;
    int t = threadIdx.x;
    int d = t & 63, pl = t >> 6;
    int p = blockIdx.y * 4 + pl;
    float v = d_spb2[b * HIDC + d] + d_cA[(b * HIDC + d) * MM];
#pragma unroll
    for (int k = 0; k < EDIM; k++)
        v = fmaf(__ldg(spEmb + p * EDIM + k), d_spw2[(b * HIDC + d) * EDIM + k], v);
    d_spT[(b * NPSP + p) * HIDC + d] = v;
}

// ---------------- fused synthesis + GELU via quartet symmetry ----------------
__global__ __launch_bounds__(256) void k_fusion(int last,
        const float* __restrict__ pW, const float* __restrict__ pB,
        float* __restrict__ out) {
    __shared__ __align__(16) float sA[HIDC][MM];
    __shared__ __align__(16) float sB[HIDC][MM];
    __shared__ float sPJ[HIDC];
    __shared__ float sRed[4][4][64];
    int b = blockIdx.x, tile = blockIdx.y, t = threadIdx.x;
    for (int i = t; i < HIDC * MM; i += 256) {
        sA[i >> 4][i & 15] = d_cA[b * HIDC * MM + i];
        sB[i >> 4][i & 15] = d_cB[b * HIDC * MM + i];
    }
    if (t < HIDC) sPJ[t] = last ? pW[t] : 0.f;
    __syncthreads();
    int sl = t & 63, dg = t >> 6;
    int q = tile * 64 + sl;
    int d0 = dg * 16;
    const float* Tb = d_spT + b * NPSP * HIDC;
    float acc[4] = {0.f, 0.f, 0.f, 0.f};
    if (q != 0) {
        int s1p = 8192 - q, s2p = 8192 + q, s3p = 16384 - q;
        int i0 = d_idx[b * SS + q]   * HIDC;
        int i1 = d_idx[b * SS + s1p] * HIDC;
        int i2 = d_idx[b * SS + s2p] * HIDC;
        int i3 = d_idx[b * SS + s3p] * HIDC;
        const float4* C4 = (const float4*)(d_mC + q * MM);
        const float4* S4 = (const float4*)(d_mS + q * MM);
        float4 c0 = C4[0], c1 = C4[1], c2 = C4[2], c3 = C4[3];
        float4 n0 = S4[0], n1 = S4[1], n2 = S4[2], n3 = S4[3];
        float* hbase = d_h + (size_t)b * SS * HIDC;
        for (int jc = 0; jc < 4; jc++) {
            int db = d0 + jc * 4;
            float T0a[4], T1a[4], T2a[4], T3a[4];
            *(float4*)T0a = *(const float4*)(Tb + i0 + db);
            *(float4*)T1a = *(const float4*)(Tb + i1 + db);
            *(float4*)T2a = *(const float4*)(Tb + i2 + db);
            *(float4*)T3a = *(const float4*)(Tb + i3 + db);
            float G0a[4], G1a[4], G2a[4], G3a[4];
#pragma unroll
            for (int cc = 0; cc < 4; cc++) {
                int d = db + cc;
                const float4* a4 = (const float4*)sA[d];
                const float4* b4 = (const float4*)sB[d];
                float4 A0 = a4[0], A1 = a4[1], A2 = a4[2], A3 = a4[3];
                float4 B0 = b4[0], B1 = b4[1], B2 = b4[2], B3 = b4[3];
                float Ue, Uo, We, Wo;
                Ue  = A0.z * c0.z;            Ue = fmaf(A1.x, c1.x, Ue);
                Ue  = fmaf(A1.z, c1.z, Ue);   Ue = fmaf(A2.x, c2.x, Ue);
                Ue  = fmaf(A2.z, c2.z, Ue);   Ue = fmaf(A3.x, c3.x, Ue);
                Ue  = fmaf(A3.z, c3.z, Ue);
                Uo  = A0.y * c0.y;            Uo = fmaf(A0.w, c0.w, Uo);
                Uo  = fmaf(A1.y, c1.y, Uo);   Uo = fmaf(A1.w, c1.w, Uo);
                Uo  = fmaf(A2.y, c2.y, Uo);   Uo = fmaf(A2.w, c2.w, Uo);
                Uo  = fmaf(A3.y, c3.y, Uo);   Uo = fmaf(A3.w, c3.w, Uo);
                We  = B0.z * n0.z;            We = fmaf(B1.x, n1.x, We);
                We  = fmaf(B1.z, n1.z, We);   We = fmaf(B2.x, n2.x, We);
                We  = fmaf(B2.z, n2.z, We);   We = fmaf(B3.x, n3.x, We);
                We  = fmaf(B3.z, n3.z, We);
                Wo  = B0.y * n0.y;            Wo = fmaf(B0.w, n0.w, Wo);
                Wo  = fmaf(B1.y, n1.y, Wo);   Wo = fmaf(B1.w, n1.w, Wo);
                Wo  = fmaf(B2.y, n2.y, Wo);   Wo = fmaf(B2.w, n2.w, Wo);
                Wo  = fmaf(B3.y, n3.y, Wo);   Wo = fmaf(B3.w, n3.w, Wo);
                float up = Ue + Uo, um = Ue - Uo, wp = We + Wo, wm = We - Wo;
                float g0 = gelu_exact(T0a[cc] + up + wp);
                float g1 = gelu_exact(T1a[cc] + um - wm);
                float g2 = gelu_exact(T2a[cc] + um + wm);
                float g3 = gelu_exact(T3a[cc] + up - wp);
                if (last) {
                    float w = sPJ[d];
                    acc[0] = fmaf(w, g0, acc[0]); acc[1] = fmaf(w, g1, acc[1]);
                    acc[2] = fmaf(w, g2, acc[2]); acc[3] = fmaf(w, g3, acc[3]);
                } else {
                    G0a[cc] = g0; G1a[cc] = g1; G2a[cc] = g2; G3a[cc] = g3;
                    acc[0] += g0; acc[1] += g1; acc[2] += g2; acc[3] += g3;
                }
            }
            if (!last) {
                *(float4*)(hbase + (size_t)q   * HIDC + db) = *(float4*)G0a;
                *(float4*)(hbase + (size_t)s1p * HIDC + db) = *(float4*)G1a;
                *(float4*)(hbase + (size_t)s2p * HIDC + db) = *(float4*)G2a;
                *(float4*)(hbase + (size_t)s3p * HIDC + db) = *(float4*)G3a;
            }
        }
    } else {
        // degenerate positions {0, 4096, 8192, 12288}, exact trig
        const float scc[4] = {1.f, 0.f, -1.f, 0.f};
        const float sss[4] = {0.f, 1.f, 0.f, -1.f};
        const int   spos[4] = {0, 4096, 8192, 12288};
        for (int j = 0; j < 4; j++) {
            int s = spos[j];
            int iv = d_idx[b * SS + s] * HIDC;
            float cosv[MM], sinv[MM];
            cosv[0] = 1.f; sinv[0] = 0.f; cosv[1] = scc[j]; sinv[1] = sss[j];
            float t2 = scc[j] * 2.f;
#pragma unroll
            for (int m = 2; m < MM; m++) {
                cosv[m] = fmaf(t2, cosv[m - 1], -cosv[m - 2]);
                sinv[m] = fmaf(t2, sinv[m - 1], -sinv[m - 2]);
            }
            for (int dd = 0; dd < 16; dd++) {
                int d = d0 + dd;
                float v = Tb[iv + d];
#pragma unroll
                for (int m = 1; m < MM; m++) {
                    v = fmaf(sA[d][m], cosv[m], v);
                    v = fmaf(sB[d][m], sinv[m], v);
                }
                float g = gelu_exact(v);
                if (last) acc[j] = fmaf(sPJ[d], g, acc[j]);
                else {
                    d_h[((size_t)b * SS + s) * HIDC + d] = g;
                    acc[j] += g;
                }
            }
        }
    }
#pragma unroll
    for (int j = 0; j < 4; j++) sRed[dg][j][sl] = acc[j];
    __syncthreads();
    if (dg == 0) {
        int ps[4];
        if (q != 0) { ps[0] = q; ps[1] = 8192 - q; ps[2] = 8192 + q; ps[3] = 16384 - q; }
        else        { ps[0] = 0; ps[1] = 4096; ps[2] = 8192; ps[3] = 12288; }
#pragma unroll
        for (int j = 0; j < 4; j++) {
            float tot = sRed[0][j][sl] + sRed[1][j][sl] + sRed[2][j][sl] + sRed[3][j][sl];
            if (last) out[b * SS + ps[j]] = tot + pB[0];
            else d_sC[b * SS + ps[j]] = tot;
        }
    }
}

extern "C" void kernel_launch(void* const* d_in, const int* in_sizes, int n_in,
                              void* d_out, int out_size) {
    const float* x     = (const float*)d_in[0];
    const float* liftW = (const float*)d_in[1];
    const float* liftB = (const float*)d_in[2];
    const float* projW = (const float*)d_in[3];
    const float* projB = (const float*)d_in[4];
    const float* spEmb = (const float*)d_in[5];
    const float* spW   = (const float*)d_in[6];
    const float* spB   = (const float*)d_in[7];
    const float* frEmb = (const float*)d_in[8];
    const float* frW   = (const float*)d_in[9];
    const float* frB   = (const float*)d_in[10];
    const float* gW1   = (const float*)d_in[11];
    const float* gB1   = (const float*)d_in[12];
    const float* gW2   = (const float*)d_in[13];
    const float* gB2   = (const float*)d_in[14];
    const float* mhWr  = (const float*)d_in[15];
    const float* mhWi  = (const float*)d_in[16];

    k_table<<<QQ * MM / 256, 256>>>();
    k_lift<<<dim3(BB, SS / 256), 256>>>(x, liftW, liftB);
    for (int l = 0; l < LL; l++) {
        k_idx<<<dim3(BB, NIDXC), 256>>>(spEmb + l * NPSP * EDIM);
        k_dft<<<dim3(BB, 32), 128>>>();
        k_coeff<<<BB, 256>>>(l, frEmb, frW, frB, spW, spB,
                             gW1, gB1, gW2, gB2, mhWr, mhWi);
        k_spt<<<dim3(BB, NPSP / 4), 256>>>(spEmb + l * NPSP * EDIM);
        k_fusion<<<dim3(BB, QQ / 64), 256>>>((l == LL - 1) ? 1 : 0,
                                             projW, projB, (float*)d_out);
    }
}

// round 11
// speedup vs baseline: 1.3358x; 1.3358x over previous
#include <cuda_runtime.h>
#include <math.h>

#define BB 16
#define CIN 3
#define HIDC 64
#define SS 16384
#define QQ 4096               // SS/4
#define MM 16
#define LL 4
#define NPSP 500
#define NPFR 200
#define EDIM 8
#define NHEADS 4
#define CHPH 16               // channels per head
#define NCHUNK 4              // DFT q-chunks (quarter-range)
#define NPART 64              // partials per channel = NCHUNK*2 halves*8 warps
#define NIDXC 8               // idx-kernel chunks

// ---------------- scratch (device globals; no allocation) ----------------
__device__ float d_tabC[SS];
__device__ float d_tabS[SS];
__device__ float d_tabC7[QQ];                            // cos(7*2*pi*q/S)
__device__ float d_tabS7[QQ];
__device__ float d_tabC8[QQ];                            // cos(8*2*pi*q/S)
__device__ float d_tabS8[QQ];
__device__ float d_h[BB * HIDC * SS];                    // 64 MB activation [b][c][s]
__device__ float d_sC[BB * SS];                          // channel-sum of h
__device__ int   d_idx[BB * SS];                         // spatial hash indices
__device__ float d_Xpart[BB * HIDC * NPART * 16];        // DFT partials (4 MB)
__device__ float d_esum[BB * NIDXC * EDIM];              // partial emb sums
__device__ float d_cA[BB * HIDC * MM];                   // fused cos coefficients
__device__ float d_cB[BB * HIDC * MM];                   // fused sin coefficients
__device__ float d_spw2[BB * HIDC * EDIM];               // gate-folded spatial W
__device__ float d_spb2[BB * HIDC];                      // gate-folded spatial b
__device__ float d_spT[BB * NPSP * HIDC];                // per-pattern sp+DC table

__device__ __forceinline__ float gelu_exact(float v) {
    return 0.5f * v * (1.0f + erff(v * 0.70710678118654752f));
}

// ---------------- trig tables (exact base angles) ----------------
__global__ void k_table() {
    int i = blockIdx.x * blockDim.x + threadIdx.x;
    if (i < SS) {
        double w = 6.283185307179586476925286766559 / (double)SS;
        double a = w * (double)i;
        d_tabC[i] = (float)cos(a);
        d_tabS[i] = (float)sin(a);
        if (i < QQ) {
            d_tabC7[i] = (float)cos(a * 7.0);
            d_tabS7[i] = (float)sin(a * 7.0);
            d_tabC8[i] = (float)cos(a * 8.0);
            d_tabS8[i] = (float)sin(a * 8.0);
        }
    }
}

// ---------------- lifting: x[B,3,S] -> h[B,64,S], plus channel-sum ----------------
__global__ __launch_bounds__(256) void k_lift(const float* __restrict__ x,
                                              const float* __restrict__ W,
                                              const float* __restrict__ bv) {
    __shared__ float sW[CIN * HIDC];
    __shared__ float sB[HIDC];
    int t = threadIdx.x;
    if (t < CIN * HIDC) sW[t] = W[t];
    if (t < HIDC) sB[t] = bv[t];
    __syncthreads();
    int b = blockIdx.x;
    int s = blockIdx.y * 256 + t;
    float x0 = x[(b * CIN + 0) * SS + s];
    float x1 = x[(b * CIN + 1) * SS + s];
    float x2 = x[(b * CIN + 2) * SS + s];
    float sc = 0.f;
#pragma unroll 8
    for (int d = 0; d < HIDC; d++) {
        float v = sB[d];
        v = fmaf(x0, sW[0 * HIDC + d], v);
        v = fmaf(x1, sW[1 * HIDC + d], v);
        v = fmaf(x2, sW[2 * HIDC + d], v);
        d_h[(b * HIDC + d) * SS + s] = v;
        sc += v;
    }
    d_sC[b * SS + s] = sc;
}

// ---------------- spatial hash indices + embedding mean partials ----------------
__global__ __launch_bounds__(256) void k_idx(const float* __restrict__ spEmb) {
    int b = blockIdx.x;
    int chunk = blockIdx.y;
    int t = threadIdx.x;
    const float* sc = d_sC + b * SS;
    float es[EDIM];
#pragma unroll
    for (int k = 0; k < EDIM; k++) es[k] = 0.f;
    const int span = SS / NIDXC;        // 2048
    for (int it = 0; it < span / 256; it++) {
        int s = chunk * span + it * 256 + t;
        int sm2 = max(s - 2, 0), sm1 = max(s - 1, 0), sp1 = min(s + 1, SS - 1);
        float w = sc[sm2] + sc[sm1] + sc[s] + sc[sp1];
        int iv = (int)(w * 31.0f);      // trunc toward zero
        iv %= NPSP; if (iv < 0) iv += NPSP;
        d_idx[b * SS + s] = iv;
        const float* e = spEmb + iv * EDIM;
#pragma unroll
        for (int k = 0; k < EDIM; k++) es[k] += __ldg(e + k);
    }
    __shared__ float red[256][EDIM];
#pragma unroll
    for (int k = 0; k < EDIM; k++) red[t][k] = es[k];
    __syncthreads();
    for (int off = 128; off > 0; off >>= 1) {
        if (t < off) {
#pragma unroll
            for (int k = 0; k < EDIM; k++) red[t][k] += red[t + off][k];
        }
        __syncthreads();
    }
    if (t < EDIM) d_esum[(b * NIDXC + chunk) * EDIM + t] = red[0][t];
}

// ---------------- 16-mode DFT: quartet fold + mode-split (8 modes/block) ---------
// blockIdx.y = chunk*2 + half; half 0 -> modes 0..7, half 1 -> modes 8..15.
// Chebyshev recurrence seeded at m=0 (1, cb) or m=8 (tab8, tab7).
// I accumulates +sum h*sin (negated later in k_coeff).
__global__ __launch_bounds__(256) void k_dft() {
    int bc = blockIdx.x;            // b*32 + channel-pair
    int b = bc >> 5, cp = bc & 31;
    int cy = blockIdx.y;            // chunk*2 + half
    int chunk = cy >> 1, half = cy & 1;
    const float* h0 = d_h + (size_t)(b * HIDC + cp * 2) * SS;
    const float* h1 = h0 + SS;
    int t = threadIdx.x;
    float aR0[8], aI0[8], aR1[8], aI1[8];
#pragma unroll
    for (int lm = 0; lm < 8; lm++) { aR0[lm] = 0.f; aI0[lm] = 0.f; aR1[lm] = 0.f; aI1[lm] = 0.f; }
#pragma unroll
    for (int it = 0; it < QQ / NCHUNK / 256; it++) {     // 4 iterations
        int q = chunk * (QQ / NCHUNK) + it * 256 + t;
        if (q == 0) {
            // degenerate positions {0, 4096, 8192, 12288}, exact trig
            float u0 = h0[0], u1 = h1[0];
            float v0 = h0[8192], v1 = h1[8192];
            float w0 = h0[4096], w1 = h1[4096];
            float z0 = h0[12288], z1 = h1[12288];
            float wzp0 = w0 + z0, wzm0 = w0 - z0;
            float wzp1 = w1 + z1, wzm1 = w1 - z1;
#pragma unroll
            for (int lm = 0; lm < 8; lm++) {
                int m = half * 8 + lm;
                aR0[lm] += u0 + ((m & 1) ? -v0 : v0);
                aR1[lm] += u1 + ((m & 1) ? -v1 : v1);
                int mm = m & 3;
                if (mm == 0)      { aR0[lm] += wzp0; aR1[lm] += wzp1; }
                else if (mm == 2) { aR0[lm] -= wzp0; aR1[lm] -= wzp1; }
                else if (mm == 1) { aI0[lm] += wzm0; aI1[lm] += wzm1; }
                else              { aI0[lm] -= wzm0; aI1[lm] -= wzm1; }
            }
            continue;
        }
        float a0 = h0[q], b0v = h0[8192 - q], c0v = h0[8192 + q], e0 = h0[16384 - q];
        float a1 = h1[q], b1v = h1[8192 - q], c1v = h1[8192 + q], e1 = h1[16384 - q];
        float p0 = a0 + e0, q0v = b0v + c0v, r0 = a0 - e0, t0v = c0v - b0v;
        float xe0 = p0 + q0v, xo0 = p0 - q0v, ye0 = r0 + t0v, yo0 = r0 - t0v;
        float p1 = a1 + e1, q1v = b1v + c1v, r1 = a1 - e1, t1v = c1v - b1v;
        float xe1 = p1 + q1v, xo1 = p1 - q1v, ye1 = r1 + t1v, yo1 = r1 - t1v;
        float cb = __ldg(&d_tabC[q]);
        float t2 = cb + cb;
        float cc, sv, cm1, sm1;
        if (half == 0) {
            cc = 1.f; sv = 0.f;
            cm1 = cb; sm1 = -__ldg(&d_tabS[q]);        // cos/sin(-theta)
        } else {
            cc  = __ldg(&d_tabC8[q]); sv  = __ldg(&d_tabS8[q]);
            cm1 = __ldg(&d_tabC7[q]); sm1 = __ldg(&d_tabS7[q]);
        }
#pragma unroll
        for (int lm = 0; lm < 8; lm++) {
            // global mode m = half*8 + lm has same parity as lm
            if (lm & 1) {
                aR0[lm] = fmaf(cc, xo0, aR0[lm]); aI0[lm] = fmaf(sv, yo0, aI0[lm]);
                aR1[lm] = fmaf(cc, xo1, aR1[lm]); aI1[lm] = fmaf(sv, yo1, aI1[lm]);
            } else {
                aR0[lm] = fmaf(cc, xe0, aR0[lm]); aI0[lm] = fmaf(sv, ye0, aI0[lm]);
                aR1[lm] = fmaf(cc, xe1, aR1[lm]); aI1[lm] = fmaf(sv, ye1, aI1[lm]);
            }
            float cn = fmaf(t2, cc, -cm1);
            float sn = fmaf(t2, sv, -sm1);
            cm1 = cc; cc = cn; sm1 = sv; sv = sn;
        }
    }
    // warp tree reduce (deterministic)
#pragma unroll
    for (int off = 16; off > 0; off >>= 1) {
#pragma unroll
        for (int lm = 0; lm < 8; lm++) {
            aR0[lm] += __shfl_down_sync(0xffffffffu, aR0[lm], off);
            aI0[lm] += __shfl_down_sync(0xffffffffu, aI0[lm], off);
            aR1[lm] += __shfl_down_sync(0xffffffffu, aR1[lm], off);
            aI1[lm] += __shfl_down_sync(0xffffffffu, aI1[lm], off);
        }
    }
    int w = t >> 5, lane = t & 31;
    if (lane == 0) {
        int part = chunk * 16 + half * 8 + w;          // 0..63
        float* o0 = d_Xpart + ((size_t)(b * HIDC + cp * 2) * NPART + part) * 16;
        float* o1 = o0 + (size_t)NPART * 16;
#pragma unroll
        for (int lm = 0; lm < 8; lm++) {
            o0[2 * lm] = aR0[lm]; o0[2 * lm + 1] = aI0[lm];
            o1[2 * lm] = aR1[lm]; o1[2 * lm + 1] = aI1[lm];
        }
    }
}

// ---------------- per-batch: reduce X, mh mixing, fr hash, gating, coefficients ----------------
__global__ __launch_bounds__(256) void k_coeff(int layer,
        const float* __restrict__ frEmb, const float* __restrict__ frW, const float* __restrict__ frB,
        const float* __restrict__ spW, const float* __restrict__ spB,
        const float* __restrict__ gW1, const float* __restrict__ gB1,
        const float* __restrict__ gW2, const float* __restrict__ gB2,
        const float* __restrict__ Wr, const float* __restrict__ Wi) {
    int b = blockIdx.x, t = threadIdx.x;
    __shared__ float sXr[HIDC][MM], sXi[HIDC][MM];
    __shared__ float sOr[HIDC][MM], sOi[HIDC][MM];
    __shared__ float sP[HIDC][MM];
    __shared__ int   smagi[MM];
    __shared__ int   sIdxFr;
    __shared__ float sEbar[EDIM];
    __shared__ float sg[3 * HIDC];
    __shared__ float sh1[HIDC];
    __shared__ float swv[3];

    // A: reduce DFT partials (fixed order), negate imag to true sign.
    // Partial layout: [c][part=chunk*16+half*8+w][16: lm*2+ri]
    for (int jg = t; jg < HIDC * 32; jg += 256) {
        int c = jg >> 5, j = jg & 31;
        int m = j >> 1, ri = j & 1;
        int half = m >> 3, lm = m & 7;
        const float* p = d_Xpart + ((size_t)(b * HIDC + c) * NPART + half * 8) * 16 + lm * 2 + ri;
        float s = 0.f;
#pragma unroll
        for (int chunk = 0; chunk < NCHUNK; chunk++)
#pragma unroll
            for (int w = 0; w < 8; w++)
                s += p[(chunk * 16 + w) * 16];
        if (ri) sXi[c][m] = -s; else sXr[c][m] = s;
    }
    __syncthreads();
    // B: spectral hash
    if (t < MM) {
        float acc = 0.f;
        for (int c = 0; c < HIDC; c++) {
            float xr = sXr[c][t], xi = sXi[c][t];
            acc += sqrtf(xr * xr + xi * xi);
        }
        float mag = acc * (1.0f / 64.0f);
        smagi[t] = (int)(mag * 1000.0f);
    }
    __syncthreads();
    if (t == 0) {
        int tot = 0;
#pragma unroll
        for (int m = 0; m < MM; m++) tot += smagi[m];
        tot %= NPFR; if (tot < 0) tot += NPFR;
        sIdxFr = tot;
    }
    if (t >= 32 && t < 32 + EDIM) {
        int k = t - 32; float s = 0.f;
        for (int p = 0; p < NIDXC; p++) s += d_esum[(b * NIDXC + p) * EDIM + k];
        sEbar[k] = s * (1.0f / (float)SS);
    }
    __syncthreads();
    // C: fr projection P[c][m]
    {
        float ef[EDIM];
        const float* er = frEmb + (layer * NPFR + sIdxFr) * EDIM;
#pragma unroll
        for (int k = 0; k < EDIM; k++) ef[k] = __ldg(er + k);
        for (int o = t; o < HIDC * MM; o += 256) {
            float v = frB[layer * HIDC * MM + o];
#pragma unroll
            for (int k = 0; k < EDIM; k++)
                v = fmaf(ef[k], frW[(layer * EDIM + k) * HIDC * MM + o], v);
            sP[o >> 4][o & 15] = v;
        }
    }
    // D: complex head mixing O = X W  (W[L][H][i][o][m])
    for (int q = t; q < HIDC * MM; q += 256) {
        int hh = q >> 8;
        int o = (q >> 4) & 15;
        int m = q & 15;
        float ar = 0.f, ai = 0.f;
        const float* wr = Wr + (((size_t)(layer * NHEADS + hh) * CHPH) * CHPH + o) * MM + m;
        const float* wi = Wi + (((size_t)(layer * NHEADS + hh) * CHPH) * CHPH + o) * MM + m;
#pragma unroll
        for (int i = 0; i < CHPH; i++) {
            float xr = sXr[hh * CHPH + i][m], xi = sXi[hh * CHPH + i][m];
            float wrv = wr[i * CHPH * MM], wiv = wi[i * CHPH * MM];
            ar = fmaf(xr, wrv, ar); ar = fmaf(-xi, wiv, ar);
            ai = fmaf(xr, wiv, ai); ai = fmaf(xi, wrv, ai);
        }
        sOr[hh * CHPH + o][m] = ar;
        sOi[hh * CHPH + o][m] = ai;
    }
    __syncthreads();
    // E: gating (analytic branch means)
    if (t < 3 * HIDC) {
        float v;
        if (t < HIDC) {
            v = spB[layer * HIDC + t];
#pragma unroll
            for (int k = 0; k < EDIM; k++)
                v = fmaf(sEbar[k], spW[(layer * EDIM + k) * HIDC + t], v);
        } else if (t < 2 * HIDC) {
            v = sOr[t - HIDC][0] * (1.0f / (float)SS);
        } else {
            v = sP[t - 2 * HIDC][0] * (1.0f / (float)SS);
        }
        sg[t] = v;
    }
    __syncthreads();
    if (t < HIDC) {
        float v = gB1[layer * 64 + t];
        for (int k = 0; k < 3 * HIDC; k++)
            v = fmaf(sg[k], gW1[(layer * 3 * HIDC + k) * 64 + t], v);
        sh1[t] = fmaxf(v, 0.f);
    }
    __syncthreads();
    if (t < 3) {
        float v = gB2[layer * 3 + t];
        for (int k = 0; k < HIDC; k++)
            v = fmaf(sh1[k], gW2[(layer * HIDC + k) * 3 + t], v);
        swv[t] = v;
    }
    __syncthreads();
    if (t == 0) {
        float mx = fmaxf(swv[0], fmaxf(swv[1], swv[2]));
        float e0 = expf(swv[0] - mx), e1 = expf(swv[1] - mx), e2 = expf(swv[2] - mx);
        float inv = 1.f / (e0 + e1 + e2);
        swv[0] = e0 * inv; swv[1] = e1 * inv; swv[2] = e2 * inv;
    }
    __syncthreads();
    // F: gate-folded synthesis coefficients
    if (t < HIDC) {
        int d = t;
        float w0 = swv[0], w1 = swv[1], w2 = swv[2];
        const float invS = 1.0f / (float)SS;
        float* A = d_cA + (b * HIDC + d) * MM;
        float* Bc = d_cB + (b * HIDC + d) * MM;
        A[0] = invS * (w1 * sOr[d][0] + w2 * sP[d][0]);
        Bc[0] = 0.f;
#pragma unroll
        for (int m = 1; m < MM; m++) {
            A[m] = 2.f * invS * (w1 * sOr[d][m] + w2 * sP[d][m]);
            Bc[m] = -2.f * invS * w1 * sOi[d][m];
        }
#pragma unroll
        for (int k = 0; k < EDIM; k++)
            d_spw2[(b * HIDC + d) * EDIM + k] = w0 * spW[(layer * EDIM + k) * HIDC + d];
        d_spb2[b * HIDC + d] = w0 * spB[layer * HIDC + d];
    }
}

// ---------------- per-layer spatial+DC table: T[b][p][d] = spb2 + A0 + emb[p]@spw2 ----
__global__ __launch_bounds__(256) void k_spt(const float* __restrict__ spEmb) {
    int b = blockIdx.x;
    int t = threadIdx.x;
    int d = t & 63, pl = t >> 6;
    int p = blockIdx.y * 4 + pl;
    float v = d_spb2[b * HIDC + d] + d_cA[(b * HIDC + d) * MM];
#pragma unroll
    for (int k = 0; k < EDIM; k++)
        v = fmaf(__ldg(spEmb + p * EDIM + k), d_spw2[(b * HIDC + d) * EDIM + k], v);
    d_spT[(b * NPSP + p) * HIDC + d] = v;
}

// ---------------- fused synthesis + GELU via quartet symmetry ----------------
// v(q)        = T0 + (Ue+Uo) + (We+Wo)
// v(S/2-q)    = T1 + (Ue-Uo) - (We-Wo)
// v(S/2+q)    = T2 + (Ue-Uo) + (We-Wo)
// v(S-q)      = T3 + (Ue+Uo) - (We+Wo)
// last==1: fold output projection; skip h/sC writes.
__global__ __launch_bounds__(256) void k_fusion(int last,
        const float* __restrict__ pW, const float* __restrict__ pB,
        float* __restrict__ out) {
    __shared__ float sA[HIDC][MM];
    __shared__ float sB[HIDC][MM];
    __shared__ float sPJ[HIDC];
    __shared__ float sRed[4][4][64];
    int b = blockIdx.x, tile = blockIdx.y, t = threadIdx.x;
    for (int i = t; i < HIDC * MM; i += 256) {
        sA[i >> 4][i & 15] = d_cA[b * HIDC * MM + i];
        sB[i >> 4][i & 15] = d_cB[b * HIDC * MM + i];
    }
    if (t < HIDC) sPJ[t] = last ? pW[t] : 0.f;
    __syncthreads();
    int sl = t & 63, dg = t >> 6;
    int q = tile * 64 + sl;
    int d0 = dg * 16;
    const float* Tb = d_spT + b * NPSP * HIDC;
    float acc[4] = {0.f, 0.f, 0.f, 0.f};
    if (q != 0) {
        int s1p = 8192 - q, s2p = 8192 + q, s3p = 16384 - q;
        int i0 = d_idx[b * SS + q]   * HIDC;
        int i1 = d_idx[b * SS + s1p] * HIDC;
        int i2 = d_idx[b * SS + s2p] * HIDC;
        int i3 = d_idx[b * SS + s3p] * HIDC;
        float c1 = d_tabC[q], sv1 = d_tabS[q];
        float cosv[MM], sinv[MM];
        cosv[0] = 1.f; sinv[0] = 0.f; cosv[1] = c1; sinv[1] = sv1;
        float t2 = c1 + c1;
#pragma unroll
        for (int m = 2; m < MM; m++) {
            cosv[m] = fmaf(t2, cosv[m - 1], -cosv[m - 2]);
            sinv[m] = fmaf(t2, sinv[m - 1], -sinv[m - 2]);
        }
        for (int dd = 0; dd < 16; dd++) {
            int d = d0 + dd;
            float Ue = 0.f, Uo = 0.f, We = 0.f, Wo = 0.f;
#pragma unroll
            for (int m = 1; m < MM; m++) {
                if (m & 1) { Uo = fmaf(sA[d][m], cosv[m], Uo); Wo = fmaf(sB[d][m], sinv[m], Wo); }
                else       { Ue = fmaf(sA[d][m], cosv[m], Ue); We = fmaf(sB[d][m], sinv[m], We); }
            }
            float up = Ue + Uo, um = Ue - Uo, wp = We + Wo, wm = We - Wo;
            float g0 = gelu_exact(Tb[i0 + d] + up + wp);
            float g1 = gelu_exact(Tb[i1 + d] + um - wm);
            float g2 = gelu_exact(Tb[i2 + d] + um + wm);
            float g3 = gelu_exact(Tb[i3 + d] + up - wp);
            if (last) {
                float w = sPJ[d];
                acc[0] = fmaf(w, g0, acc[0]); acc[1] = fmaf(w, g1, acc[1]);
                acc[2] = fmaf(w, g2, acc[2]); acc[3] = fmaf(w, g3, acc[3]);
            } else {
                float* hp = d_h + (b * HIDC + d) * SS;
                hp[q] = g0; hp[s1p] = g1; hp[s2p] = g2; hp[s3p] = g3;
                acc[0] += g0; acc[1] += g1; acc[2] += g2; acc[3] += g3;
            }
        }
    } else {
        // degenerate positions {0, 4096, 8192, 12288}, exact trig
        const float scc[4] = {1.f, 0.f, -1.f, 0.f};
        const float sss[4] = {0.f, 1.f, 0.f, -1.f};
        const int   spos[4] = {0, 4096, 8192, 12288};
        for (int j = 0; j < 4; j++) {
            int s = spos[j];
            int iv = d_idx[b * SS + s] * HIDC;
            float cosv[MM], sinv[MM];
            cosv[0] = 1.f; sinv[0] = 0.f; cosv[1] = scc[j]; sinv[1] = sss[j];
            float t2 = scc[j] * 2.f;
#pragma unroll
            for (int m = 2; m < MM; m++) {
                cosv[m] = fmaf(t2, cosv[m - 1], -cosv[m - 2]);
                sinv[m] = fmaf(t2, sinv[m - 1], -sinv[m - 2]);
            }
            for (int dd = 0; dd < 16; dd++) {
                int d = d0 + dd;
                float v = Tb[iv + d];
#pragma unroll
                for (int m = 1; m < MM; m++) {
                    v = fmaf(sA[d][m], cosv[m], v);
                    v = fmaf(sB[d][m], sinv[m], v);
                }
                float g = gelu_exact(v);
                if (last) acc[j] = fmaf(sPJ[d], g, acc[j]);
                else { d_h[(b * HIDC + d) * SS + s] = g; acc[j] += g; }
            }
        }
    }
#pragma unroll
    for (int j = 0; j < 4; j++) sRed[dg][j][sl] = acc[j];
    __syncthreads();
    if (dg == 0) {
        int ps[4];
        if (q != 0) { ps[0] = q; ps[1] = 8192 - q; ps[2] = 8192 + q; ps[3] = 16384 - q; }
        else        { ps[0] = 0; ps[1] = 4096; ps[2] = 8192; ps[3] = 12288; }
#pragma unroll
        for (int j = 0; j < 4; j++) {
            float tot = sRed[0][j][sl] + sRed[1][j][sl] + sRed[2][j][sl] + sRed[3][j][sl];
            if (last) out[b * SS + ps[j]] = tot + pB[0];
            else d_sC[b * SS + ps[j]] = tot;
        }
    }
}

extern "C" void kernel_launch(void* const* d_in, const int* in_sizes, int n_in,
                              void* d_out, int out_size) {
    const float* x     = (const float*)d_in[0];
    const float* liftW = (const float*)d_in[1];
    const float* liftB = (const float*)d_in[2];
    const float* projW = (const float*)d_in[3];
    const float* projB = (const float*)d_in[4];
    const float* spEmb = (const float*)d_in[5];
    const float* spW   = (const float*)d_in[6];
    const float* spB   = (const float*)d_in[7];
    const float* frEmb = (const float*)d_in[8];
    const float* frW   = (const float*)d_in[9];
    const float* frB   = (const float*)d_in[10];
    const float* gW1   = (const float*)d_in[11];
    const float* gB1   = (const float*)d_in[12];
    const float* gW2   = (const float*)d_in[13];
    const float* gB2   = (const float*)d_in[14];
    const float* mhWr  = (const float*)d_in[15];
    const float* mhWi  = (const float*)d_in[16];

    k_table<<<SS / 256, 256>>>();
    k_lift<<<dim3(BB, SS / 256), 256>>>(x, liftW, liftB);
    for (int l = 0; l < LL; l++) {
        k_idx<<<dim3(BB, NIDXC), 256>>>(spEmb + l * NPSP * EDIM);
        k_dft<<<dim3(BB * 32, NCHUNK * 2), 256>>>();
        k_coeff<<<BB, 256>>>(l, frEmb, frW, frB, spW, spB,
                             gW1, gB1, gW2, gB2, mhWr, mhWi);
        k_spt<<<dim3(BB, NPSP / 4), 256>>>(spEmb + l * NPSP * EDIM);
        k_fusion<<<dim3(BB, QQ / 64), 256>>>((l == LL - 1) ? 1 : 0,
                                             projW, projB, (float*)d_out);
    }
}